// round 15
// baseline (speedup 1.0000x reference)
#include <cuda_runtime.h>
#include <cuda_bf16.h>
#include <cstdint>

#define TOKENS 16384
#define HDIM   1024
#define FDIM   4096
#define WSZ    (FDIM*HDIM)

// ---------------- scratch (static device, no allocations) ----------------
// Tiled bf16 layout for all GEMM operands: tile = 128 rows x 64 k = 16384 B,
// tiles ordered [row_block][k_block]. Within a tile, row r (128 B) holds 8
// 16B chunks, physically at chunk c ^ (r & 7)  -> ldmatrix conflict-free.
__device__ __align__(1024) __nv_bfloat16 g_xq  [(size_t)TOKENS*HDIM];   // 32 MB
__device__ __align__(1024) __nv_bfloat16 g_wupq[WSZ];                   //  8 MB
__device__ __align__(1024) __nv_bfloat16 g_wdnq[WSZ];                   //  8 MB
__device__ __align__(1024) __nv_bfloat16 g_h2q [(size_t)TOKENS*FDIM];   // 128 MB
__device__ int16_t g_up [(size_t)TOKENS*FDIM];   // 128 MB GEMM1 result (exact ints, linear)
__device__ float  g_mul1[TOKENS];
__device__ int    g_rowmax[TOKENS];              // float bits, >= 0
__device__ float  g_part[2048];
__device__ float  g_mw[2];

// byte address of bf16 element (row R, col k) in tiled layout (KB k-blocks)
__device__ __forceinline__ size_t tiled_off16(int R, int k, int KB) {
    int r = R & 127, mb = R >> 7, kb = k >> 6;
    int c  = (k & 63) >> 3;           // chunk 0..7
    int c4 = c ^ (r & 7);
    return ((size_t)(mb * KB + kb) << 14) + (size_t)(r * 128 + (c4 << 4) + ((k & 7) << 1));
}

// ---------------- PTX helpers ----------------
__device__ __forceinline__ uint32_t smem_u32(const void* p) {
    uint32_t a;
    asm("{ .reg .u64 t; cvta.to.shared.u64 t, %1; cvt.u32.u64 %0, t; }" : "=r"(a) : "l"(p));
    return a;
}
__device__ __forceinline__ void mma_bf16(float* c, const uint32_t* a, uint32_t b0, uint32_t b1) {
    asm volatile(
        "mma.sync.aligned.m16n8k16.row.col.f32.bf16.bf16.f32 "
        "{%0,%1,%2,%3}, {%4,%5,%6,%7}, {%8,%9}, {%0,%1,%2,%3};"
        : "+f"(c[0]), "+f"(c[1]), "+f"(c[2]), "+f"(c[3])
        : "r"(a[0]), "r"(a[1]), "r"(a[2]), "r"(a[3]), "r"(b0), "r"(b1));
}
__device__ __forceinline__ void ldm_x4(uint32_t* r, uint32_t addr) {
    asm volatile("ldmatrix.sync.aligned.m8n8.x4.shared.b16 {%0,%1,%2,%3}, [%4];"
        : "=r"(r[0]), "=r"(r[1]), "=r"(r[2]), "=r"(r[3]) : "r"(addr));
}
__device__ __forceinline__ void cp_bulk(uint32_t dst, const void* src, uint32_t bytes, uint32_t mbar) {
    asm volatile(
        "cp.async.bulk.shared::cta.global.mbarrier::complete_tx::bytes [%0], [%1], %2, [%3];"
        :: "r"(dst), "l"(src), "r"(bytes), "r"(mbar) : "memory");
}
#define MBARRIER_INIT(addr, cnt) \
    asm volatile("mbarrier.init.shared.b64 [%0], %1;" :: "r"((uint32_t)(addr)), "r"((uint32_t)(cnt)) : "memory")
#define MBARRIER_EXPECT_TX(addr, tx) \
    asm volatile("mbarrier.arrive.expect_tx.shared.b64 _, [%0], %1;" :: "r"((uint32_t)(addr)), "r"((uint32_t)(tx)) : "memory")
#define MBARRIER_ARRIVE(addr) \
    asm volatile("mbarrier.arrive.shared.b64 _, [%0];" :: "r"((uint32_t)(addr)) : "memory")
#define MBARRIER_WAIT_PARITY(addr, parity) do {                                   \
    uint32_t _mbar = (uint32_t)(addr);                                            \
    uint32_t _par  = (uint32_t)(parity);                                          \
    asm volatile(                                                                 \
        "{\n\t.reg .pred P1;\n\t"                                                 \
        "WAIT_LOOP_%=:\n\t"                                                       \
        "mbarrier.try_wait.parity.acquire.cta.shared::cta.b64 P1, [%0], %1, 0x989680;\n\t" \
        "@P1 bra.uni WAIT_DONE_%=;\n\t"                                           \
        "bra.uni WAIT_LOOP_%=;\n\t"                                               \
        "WAIT_DONE_%=:\n\t}"                                                      \
        :: "r"(_mbar), "r"(_par) : "memory");                                     \
} while (0)
#define MBARRIER_WAIT_PARITY_RELAXED(addr, parity) do {                           \
    uint32_t _mbar = (uint32_t)(addr);                                            \
    uint32_t _par  = (uint32_t)(parity);                                          \
    asm volatile(                                                                 \
        "{\n\t.reg .pred P1;\n\t"                                                 \
        "WAIT_LOOP_%=:\n\t"                                                       \
        "mbarrier.try_wait.parity.relaxed.cta.shared::cta.b64 P1, [%0], %1, 0x989680;\n\t" \
        "@P1 bra.uni WAIT_DONE_%=;\n\t"                                           \
        "bra.uni WAIT_LOOP_%=;\n\t"                                               \
        "WAIT_DONE_%=:\n\t}"                                                      \
        :: "r"(_mbar), "r"(_par) : "memory");                                     \
} while (0)

// ---------------- elementwise kernels ----------------

__global__ void k_reduce_abs(const float* __restrict__ wup, const float* __restrict__ wdn) {
    __shared__ float sh[256];
    int b = blockIdx.x;
    const float4* p = (const float4*)((b < 1024) ? wup : wdn);
    int bb = b & 1023;
    float s = 0.f;
    int base = bb * 1024 + threadIdx.x;
#pragma unroll
    for (int i = 0; i < 4; i++) {
        float4 v = p[base + i * 256];
        s += fabsf(v.x) + fabsf(v.y) + fabsf(v.z) + fabsf(v.w);
    }
    sh[threadIdx.x] = s; __syncthreads();
    for (int o = 128; o > 0; o >>= 1) {
        if (threadIdx.x < o) sh[threadIdx.x] += sh[threadIdx.x + o];
        __syncthreads();
    }
    if (threadIdx.x == 0) g_part[b] = sh[0];
}

__global__ void k_finalize_mw() {
    __shared__ float sh[256];
    for (int half = 0; half < 2; half++) {
        float s = 0.f;
        for (int i = threadIdx.x; i < 1024; i += 256) s += g_part[half * 1024 + i];
        sh[threadIdx.x] = s; __syncthreads();
        for (int o = 128; o > 0; o >>= 1) {
            if (threadIdx.x < o) sh[threadIdx.x] += sh[threadIdx.x + o];
            __syncthreads();
        }
        if (threadIdx.x == 0) g_mw[half] = fmaxf(sh[0] / (float)WSZ, 1e-5f);
        __syncthreads();
    }
}

// ternarize 8 consecutive k per thread -> one full 16B tiled chunk store
__device__ __forceinline__ void tern8(const float* __restrict__ w, __nv_bfloat16* out,
                                      int g, int K, int KB, float s) {
    int R = g / (K >> 3), k = (g % (K >> 3)) << 3;
    const float4* src = (const float4*)(w + (size_t)R * K + k);
    float4 v0 = src[0], v1 = src[1];
    uint32_t pk[4];
    float e[8] = {v0.x, v0.y, v0.z, v0.w, v1.x, v1.y, v1.z, v1.w};
#pragma unroll
    for (int j = 0; j < 4; j++) {
        float q0 = rintf(fminf(fmaxf(e[2*j]   * s, -1.f), 1.f));
        float q1 = rintf(fminf(fmaxf(e[2*j+1] * s, -1.f), 1.f));
        __nv_bfloat162 b2 = __floats2bfloat162_rn(q0, q1);
        pk[j] = *(uint32_t*)&b2;
    }
    *(uint4*)((char*)out + tiled_off16(R, k, KB)) = make_uint4(pk[0], pk[1], pk[2], pk[3]);
}

// fused: blocks [0,2048) ternarize w_up; blocks [2048, 2048+TOKENS) rmsnorm+quant
__global__ void k_tern_rms(const float* __restrict__ wup,
                           const float* __restrict__ x, const float* __restrict__ nw) {
    if (blockIdx.x < 2048) {
        int g = blockIdx.x * 256 + threadIdx.x;     // 8-elem group over WSZ/8
        tern8(wup, g_wupq, g, HDIM, HDIM >> 6, 1.0f / g_mw[0]);
        return;
    }
    __shared__ float sh[256];
    __shared__ float s_inv, s_scale;
    int t = blockIdx.x - 2048, tid = threadIdx.x;
    float4 v = ((const float4*)(x + (size_t)t * HDIM))[tid];
    float4 w = ((const float4*)nw)[tid];
    float ss = v.x * v.x + v.y * v.y + v.z * v.z + v.w * v.w;
    sh[tid] = ss; __syncthreads();
    for (int o = 128; o > 0; o >>= 1) { if (tid < o) sh[tid] += sh[tid + o]; __syncthreads(); }
    if (tid == 0) s_inv = 1.0f / sqrtf(sh[0] * (1.0f / HDIM) + 1e-6f);
    __syncthreads();
    float inv = s_inv;
    float h0 = v.x * inv * w.x, h1 = v.y * inv * w.y, h2 = v.z * inv * w.z, h3 = v.w * inv * w.w;
    float m = fmaxf(fmaxf(fabsf(h0), fabsf(h1)), fmaxf(fabsf(h2), fabsf(h3)));
    sh[tid] = m; __syncthreads();
    for (int o = 128; o > 0; o >>= 1) { if (tid < o) sh[tid] = fmaxf(sh[tid], sh[tid + o]); __syncthreads(); }
    if (tid == 0) {
        float cm = fmaxf(sh[0], 1e-5f);
        s_scale = 127.0f / cm;
        g_mul1[t] = (cm / 127.0f) * g_mw[0];
        g_rowmax[t] = 0;
    }
    __syncthreads();
    float sc = s_scale;
    float q0 = rintf(fminf(fmaxf(h0 * sc, -128.f), 127.f));
    float q1 = rintf(fminf(fmaxf(h1 * sc, -128.f), 127.f));
    float q2 = rintf(fminf(fmaxf(h2 * sc, -128.f), 127.f));
    float q3 = rintf(fminf(fmaxf(h3 * sc, -128.f), 127.f));
    char* p = (char*)g_xq + tiled_off16(t, 4 * tid, HDIM >> 6);
    *(__nv_bfloat162*)p       = __floats2bfloat162_rn(q0, q1);
    *(__nv_bfloat162*)(p + 4) = __floats2bfloat162_rn(q2, q3);
}

__global__ void k_ternarize_dn(const float* __restrict__ wdn) {
    int g = blockIdx.x * 256 + threadIdx.x;
    tern8(wdn, g_wdnq, g, FDIM, FDIM >> 6, 1.0f / g_mw[1]);
}

// relu^2 + per-token absmax int8 quant; 16 elems (32B) per thread.
__global__ void k_relu2_quant() {
    size_t i = (size_t)blockIdx.x * 256 + threadIdx.x;    // group-of-16 index
    int t = (int)(i >> 8);                                // 256 groups per row
    float mul1 = g_mul1[t];
    float rm = __int_as_float(g_rowmax[t]) * mul1;
    float sc2 = 127.0f / fmaxf(rm * rm, 1e-5f);
    const int4* src = (const int4*)(g_up + i * 16);
    int f = (int)((i & 255) << 4);
#pragma unroll
    for (int half = 0; half < 2; half++) {
        int4 u = src[half];
        uint32_t pk[4];
        const uint32_t* uw = (const uint32_t*)&u;
#pragma unroll
        for (int j = 0; j < 4; j++) {
            int lo = (int)(short)(uw[j] & 0xFFFF);
            int hi = (int)(short)(uw[j] >> 16);
            float a0 = fmaxf((float)lo, 0.f) * mul1;
            float a1 = fmaxf((float)hi, 0.f) * mul1;
            float q0 = rintf(fminf(a0 * a0 * sc2, 127.f));
            float q1 = rintf(fminf(a1 * a1 * sc2, 127.f));
            __nv_bfloat162 b2 = __floats2bfloat162_rn(q0, q1);
            pk[j] = *(uint32_t*)&b2;
        }
        *(uint4*)((char*)g_h2q + tiled_off16(t, f + half * 8, FDIM >> 6)) =
            make_uint4(pk[0], pk[1], pk[2], pk[3]);
    }
}

// ---------------- bf16 mma.sync GEMM, bulk-copy + mbarrier pipeline ----------------
// Tile 128x128x64; 8 warps = 2(M) x 4(N); warp tile 64x32; 3 stages; 2 CTAs/SM.
// NSUB consecutive mb sub-tiles per CTA at fixed nb; the stage pipeline runs
// continuously across sub-tile boundaries (epilogue overlaps next tile's fill).
// EPI==1: store int16 (exact) to g_up + fused per-row relu-max.
// EPI==2: out = C*mul2[m] + resid (float).

#define STAGES    3
#define STAGE_B   32768
#define GEMM_SMEM (STAGES*STAGE_B)

template <int KTOT, int EPI, int NSUB>
__global__ void __launch_bounds__(256, 2)
k_gemm(const float* __restrict__ resid, float* __restrict__ out2) {
    extern __shared__ __align__(128) int8_t smem[];
    __shared__ __align__(8) uint64_t s_bar[2 * STAGES];
    __shared__ int s_rowmax[128];

    const __nv_bfloat16* A = (EPI == 1) ? g_xq   : g_h2q;
    const __nv_bfloat16* B = (EPI == 1) ? g_wupq : g_wdnq;
    const int KIT = KTOT / 64;       // k-iters per sub-tile (power of 2)
    const int KB  = KTOT / 64;
    const int GKIT = NSUB * KIT;     // total k-iters per CTA

    int tid = threadIdx.x, wid = tid >> 5, lane = tid & 31;
    int wm = wid & 1, wn = wid >> 1;
    int mb0 = blockIdx.y * NSUB, nb = blockIdx.x;
    int n0 = nb * 128;
    int tg = lane & 3, gp = lane >> 2;
    uint32_t sbase = smem_u32(smem);
    uint32_t barb  = smem_u32(s_bar);

    if (EPI == 1 && tid < 128) s_rowmax[tid] = 0;
    if (tid == 0) {
#pragma unroll
        for (int s = 0; s < STAGES; s++) {
            MBARRIER_INIT(barb + s * 8, 1);             // full: tx-based
            MBARRIER_INIT(barb + (STAGES + s) * 8, 8);  // empty: one arrive per warp
        }
        asm volatile("fence.proxy.async.shared::cta;" ::: "memory");
    }
    __syncthreads();

    int aRow = wm * 64 + (lane & 15);
    int aCsel = lane >> 4;
    int bRow = wn * 32 + ((lane >> 3) & 1) * 8 + (lane & 7);
    int bCsel = lane >> 4;

    float acc[4][4][4];
#pragma unroll
    for (int i = 0; i < 4; i++)
#pragma unroll
        for (int j = 0; j < 4; j++)
#pragma unroll
            for (int r = 0; r < 4; r++) acc[i][j][r] = 0.f;

    int pstage = 0, pphase = 1;
    int cphase = 0;

    // gk: global k-iter 0..GKIT-1; sub = gk/KIT, kit = gk%KIT (shifts/masks)
    auto produce = [&](int gk) {
        int mbk = mb0 + (gk / KIT);          // KIT is a compile-time power of 2
        int kit = gk & (KIT - 1);
        uint32_t fb = barb + pstage * 8;
        MBARRIER_WAIT_PARITY_RELAXED(barb + (STAGES + pstage) * 8, pphase);
        MBARRIER_EXPECT_TX(fb, 32768u);
        uint32_t dst = sbase + (uint32_t)pstage * STAGE_B;
        cp_bulk(dst,          (const char*)A + ((size_t)(mbk * KB + kit) << 14), 16384u, fb);
        cp_bulk(dst + 16384u, (const char*)B + ((size_t)(nb * KB + kit) << 14), 16384u, fb);
        if (++pstage == STAGES) { pstage = 0; pphase ^= 1; }
    };

    if (tid == 0) {
        produce(0);
        produce(1);
    }

    int cur = 0;
    for (int gk = 0; gk < GKIT; gk++) {
        if (tid == 0 && gk + STAGES - 1 < GKIT) produce(gk + STAGES - 1);

        MBARRIER_WAIT_PARITY(barb + cur * 8, cphase);
        uint32_t sA = sbase + (uint32_t)cur * STAGE_B;
        uint32_t sB = sA + 16384u;

#pragma unroll
        for (int ks = 0; ks < 4; ks++) {
            uint32_t a[4][4], b[2][4];
#pragma unroll
            for (int mt = 0; mt < 4; mt++) {
                int row = aRow + mt * 16;
                int c4 = (2 * ks + aCsel) ^ (row & 7);
                ldm_x4(a[mt], sA + row * 128 + (c4 << 4));
            }
#pragma unroll
            for (int np = 0; np < 2; np++) {
                int row = bRow + np * 16;
                int c4 = (2 * ks + bCsel) ^ (row & 7);
                ldm_x4(b[np], sB + row * 128 + (c4 << 4));
            }
            if (ks == 3 && lane == 0) MBARRIER_ARRIVE(barb + (STAGES + cur) * 8);
#pragma unroll
            for (int mt = 0; mt < 4; mt++)
#pragma unroll
                for (int np = 0; np < 2; np++)
#pragma unroll
                    for (int h = 0; h < 2; h++)
                        mma_bf16(acc[mt][np * 2 + h], a[mt], b[np][h], b[np][h + 2]);
        }
        if (++cur == STAGES) { cur = 0; cphase ^= 1; }

        // ---------------- sub-tile epilogue flush ----------------
        if ((gk & (KIT - 1)) == KIT - 1) {
            int m0 = (mb0 + (gk / KIT)) * 128;
            if (EPI == 1) {
#pragma unroll
                for (int mt = 0; mt < 4; mt++) {
                    int lr0 = wm * 64 + mt * 16 + gp;
                    float mx0 = 0.f, mx1 = 0.f;
#pragma unroll
                    for (int nt = 0; nt < 4; nt++) {
                        int col = n0 + wn * 32 + nt * 8 + tg * 2;
                        int16_t* d0 = g_up + (size_t)(m0 + lr0) * FDIM + col;
                        int16_t* d1 = g_up + (size_t)(m0 + lr0 + 8) * FDIM + col;
                        int v00 = __float2int_rn(acc[mt][nt][0]);
                        int v01 = __float2int_rn(acc[mt][nt][1]);
                        int v10 = __float2int_rn(acc[mt][nt][2]);
                        int v11 = __float2int_rn(acc[mt][nt][3]);
                        *(uint32_t*)d0 = (uint32_t)(v00 & 0xFFFF) | ((uint32_t)v01 << 16);
                        *(uint32_t*)d1 = (uint32_t)(v10 & 0xFFFF) | ((uint32_t)v11 << 16);
                        mx0 = fmaxf(mx0, fmaxf(acc[mt][nt][0], acc[mt][nt][1]));
                        mx1 = fmaxf(mx1, fmaxf(acc[mt][nt][2], acc[mt][nt][3]));
                    }
                    mx0 = fmaxf(mx0, __shfl_xor_sync(0xFFFFFFFFu, mx0, 1));
                    mx0 = fmaxf(mx0, __shfl_xor_sync(0xFFFFFFFFu, mx0, 2));
                    mx1 = fmaxf(mx1, __shfl_xor_sync(0xFFFFFFFFu, mx1, 1));
                    mx1 = fmaxf(mx1, __shfl_xor_sync(0xFFFFFFFFu, mx1, 2));
                    if (tg == 0) {
                        atomicMax(&s_rowmax[lr0], __float_as_int(mx0));
                        atomicMax(&s_rowmax[lr0 + 8], __float_as_int(mx1));
                    }
                }
                __syncthreads();
                if (tid < 128) {
                    atomicMax(&g_rowmax[m0 + tid], s_rowmax[tid]);
                    s_rowmax[tid] = 0;
                }
                if (NSUB > 1) __syncthreads();
            } else {
#pragma unroll
                for (int mt = 0; mt < 4; mt++) {
                    int r0 = m0 + wm * 64 + mt * 16 + gp;
                    int r1 = r0 + 8;
                    float m1a = g_mul1[r0], m1b = g_mul1[r1];
                    float rma = __int_as_float(g_rowmax[r0]) * m1a;
                    float rmb = __int_as_float(g_rowmax[r1]) * m1b;
                    float mul2a = (fmaxf(rma * rma, 1e-5f) / 127.0f) * g_mw[1];
                    float mul2b = (fmaxf(rmb * rmb, 1e-5f) / 127.0f) * g_mw[1];
#pragma unroll
                    for (int nt = 0; nt < 4; nt++) {
                        int col = n0 + wn * 32 + nt * 8 + tg * 2;
                        const float2 ra = *(const float2*)(resid + (size_t)r0 * HDIM + col);
                        const float2 rb = *(const float2*)(resid + (size_t)r1 * HDIM + col);
                        float2 oa, ob;
                        oa.x = acc[mt][nt][0] * mul2a + ra.x;
                        oa.y = acc[mt][nt][1] * mul2a + ra.y;
                        ob.x = acc[mt][nt][2] * mul2b + rb.x;
                        ob.y = acc[mt][nt][3] * mul2b + rb.y;
                        *(float2*)(out2 + (size_t)r0 * HDIM + col) = oa;
                        *(float2*)(out2 + (size_t)r1 * HDIM + col) = ob;
                    }
                }
            }
            if (NSUB > 1 && gk + 1 < GKIT) {
#pragma unroll
                for (int i = 0; i < 4; i++)
#pragma unroll
                    for (int j = 0; j < 4; j++)
#pragma unroll
                        for (int r = 0; r < 4; r++) acc[i][j][r] = 0.f;
            }
        }
    }
}

// ---------------- launch ----------------
extern "C" void kernel_launch(void* const* d_in, const int* in_sizes, int n_in,
                              void* d_out, int out_size) {
    const float* x   = (const float*)d_in[0];
    const float* nw  = (const float*)d_in[1];
    const float* wup = (const float*)d_in[2];
    const float* wdn = (const float*)d_in[3];
    float* out = (float*)d_out;

    cudaFuncSetAttribute(k_gemm<1024, 1, 2>, cudaFuncAttributeMaxDynamicSharedMemorySize, GEMM_SMEM);
    cudaFuncSetAttribute(k_gemm<4096, 2, 1>, cudaFuncAttributeMaxDynamicSharedMemorySize, GEMM_SMEM);

    k_reduce_abs<<<2048, 256>>>(wup, wdn);                                   // 1
    k_finalize_mw<<<1, 256>>>();                                             // 2
    k_tern_rms<<<2048 + TOKENS, 256>>>(wup, x, nw);                          // 3
    k_gemm<1024, 1, 2><<<dim3(FDIM / 128, TOKENS / 256), 256, GEMM_SMEM>>>(nullptr, nullptr);  // 4 (profiled)
    k_ternarize_dn<<<2048, 256>>>(wdn);                                      // 5
    k_relu2_quant<<<(int)((size_t)TOKENS * FDIM / 16 / 256), 256>>>();       // 6
    k_gemm<4096, 2, 1><<<dim3(HDIM / 128, TOKENS / 128), 256, GEMM_SMEM>>>(x, out);            // 7
}

// round 16
// speedup vs baseline: 1.0677x; 1.0677x over previous
#include <cuda_runtime.h>
#include <cuda_bf16.h>
#include <cstdint>

#define TOKENS 16384
#define HDIM   1024
#define FDIM   4096
#define WSZ    (FDIM*HDIM)

// ---------------- scratch (static device, no allocations) ----------------
// Tiled bf16 layout for all GEMM operands: tile = 128 rows x 64 k = 16384 B,
// tiles ordered [row_block][k_block]. Within a tile, row r (128 B) holds 8
// 16B chunks, physically at chunk c ^ (r & 7)  -> ldmatrix conflict-free.
__device__ __align__(1024) __nv_bfloat16 g_xq  [(size_t)TOKENS*HDIM];   // 32 MB
__device__ __align__(1024) __nv_bfloat16 g_wupq[WSZ];                   //  8 MB
__device__ __align__(1024) __nv_bfloat16 g_wdnq[WSZ];                   //  8 MB
__device__ __align__(1024) __nv_bfloat16 g_h2q [(size_t)TOKENS*FDIM];   // 128 MB
__device__ int16_t g_up [(size_t)TOKENS*FDIM];   // 128 MB GEMM1 result (exact ints, linear)
__device__ float  g_mul1[TOKENS];
__device__ int    g_rowmax[TOKENS];              // float bits, >= 0
__device__ float  g_part[2048];
__device__ float  g_mw[2];

// byte address of bf16 element (row R, col k) in tiled layout (KB k-blocks)
__device__ __forceinline__ size_t tiled_off16(int R, int k, int KB) {
    int r = R & 127, mb = R >> 7, kb = k >> 6;
    int c  = (k & 63) >> 3;           // chunk 0..7
    int c4 = c ^ (r & 7);
    return ((size_t)(mb * KB + kb) << 14) + (size_t)(r * 128 + (c4 << 4) + ((k & 7) << 1));
}

// ---------------- PTX helpers ----------------
__device__ __forceinline__ uint32_t smem_u32(const void* p) {
    uint32_t a;
    asm("{ .reg .u64 t; cvta.to.shared.u64 t, %1; cvt.u32.u64 %0, t; }" : "=r"(a) : "l"(p));
    return a;
}
__device__ __forceinline__ void mma_bf16(float* c, const uint32_t* a, uint32_t b0, uint32_t b1) {
    asm volatile(
        "mma.sync.aligned.m16n8k16.row.col.f32.bf16.bf16.f32 "
        "{%0,%1,%2,%3}, {%4,%5,%6,%7}, {%8,%9}, {%0,%1,%2,%3};"
        : "+f"(c[0]), "+f"(c[1]), "+f"(c[2]), "+f"(c[3])
        : "r"(a[0]), "r"(a[1]), "r"(a[2]), "r"(a[3]), "r"(b0), "r"(b1));
}
__device__ __forceinline__ void ldm_x4(uint32_t* r, uint32_t addr) {
    asm volatile("ldmatrix.sync.aligned.m8n8.x4.shared.b16 {%0,%1,%2,%3}, [%4];"
        : "=r"(r[0]), "=r"(r[1]), "=r"(r[2]), "=r"(r[3]) : "r"(addr));
}
__device__ __forceinline__ void cp_bulk(uint32_t dst, const void* src, uint32_t bytes, uint32_t mbar) {
    asm volatile(
        "cp.async.bulk.shared::cta.global.mbarrier::complete_tx::bytes [%0], [%1], %2, [%3];"
        :: "r"(dst), "l"(src), "r"(bytes), "r"(mbar) : "memory");
}
#define MBARRIER_INIT(addr, cnt) \
    asm volatile("mbarrier.init.shared.b64 [%0], %1;" :: "r"((uint32_t)(addr)), "r"((uint32_t)(cnt)) : "memory")
#define MBARRIER_EXPECT_TX(addr, tx) \
    asm volatile("mbarrier.arrive.expect_tx.shared.b64 _, [%0], %1;" :: "r"((uint32_t)(addr)), "r"((uint32_t)(tx)) : "memory")
#define MBARRIER_ARRIVE(addr) \
    asm volatile("mbarrier.arrive.shared.b64 _, [%0];" :: "r"((uint32_t)(addr)) : "memory")
#define MBARRIER_WAIT_PARITY(addr, parity) do {                                   \
    uint32_t _mbar = (uint32_t)(addr);                                            \
    uint32_t _par  = (uint32_t)(parity);                                          \
    asm volatile(                                                                 \
        "{\n\t.reg .pred P1;\n\t"                                                 \
        "WAIT_LOOP_%=:\n\t"                                                       \
        "mbarrier.try_wait.parity.acquire.cta.shared::cta.b64 P1, [%0], %1, 0x989680;\n\t" \
        "@P1 bra.uni WAIT_DONE_%=;\n\t"                                           \
        "bra.uni WAIT_LOOP_%=;\n\t"                                               \
        "WAIT_DONE_%=:\n\t}"                                                      \
        :: "r"(_mbar), "r"(_par) : "memory");                                     \
} while (0)
#define MBARRIER_WAIT_PARITY_RELAXED(addr, parity) do {                           \
    uint32_t _mbar = (uint32_t)(addr);                                            \
    uint32_t _par  = (uint32_t)(parity);                                          \
    asm volatile(                                                                 \
        "{\n\t.reg .pred P1;\n\t"                                                 \
        "WAIT_LOOP_%=:\n\t"                                                       \
        "mbarrier.try_wait.parity.relaxed.cta.shared::cta.b64 P1, [%0], %1, 0x989680;\n\t" \
        "@P1 bra.uni WAIT_DONE_%=;\n\t"                                           \
        "bra.uni WAIT_LOOP_%=;\n\t"                                               \
        "WAIT_DONE_%=:\n\t}"                                                      \
        :: "r"(_mbar), "r"(_par) : "memory");                                     \
} while (0)

// ---------------- elementwise kernels ----------------

__global__ void k_reduce_abs(const float* __restrict__ wup, const float* __restrict__ wdn) {
    __shared__ float sh[256];
    int b = blockIdx.x;
    const float4* p = (const float4*)((b < 1024) ? wup : wdn);
    int bb = b & 1023;
    float s = 0.f;
    int base = bb * 1024 + threadIdx.x;
#pragma unroll
    for (int i = 0; i < 4; i++) {
        float4 v = p[base + i * 256];
        s += fabsf(v.x) + fabsf(v.y) + fabsf(v.z) + fabsf(v.w);
    }
    sh[threadIdx.x] = s; __syncthreads();
    for (int o = 128; o > 0; o >>= 1) {
        if (threadIdx.x < o) sh[threadIdx.x] += sh[threadIdx.x + o];
        __syncthreads();
    }
    if (threadIdx.x == 0) g_part[b] = sh[0];
}

__global__ void k_finalize_mw() {
    __shared__ float sh[256];
    for (int half = 0; half < 2; half++) {
        float s = 0.f;
        for (int i = threadIdx.x; i < 1024; i += 256) s += g_part[half * 1024 + i];
        sh[threadIdx.x] = s; __syncthreads();
        for (int o = 128; o > 0; o >>= 1) {
            if (threadIdx.x < o) sh[threadIdx.x] += sh[threadIdx.x + o];
            __syncthreads();
        }
        if (threadIdx.x == 0) g_mw[half] = fmaxf(sh[0] / (float)WSZ, 1e-5f);
        __syncthreads();
    }
}

// ternarize 8 consecutive k per thread -> one full 16B tiled chunk store
__device__ __forceinline__ void tern8(const float* __restrict__ w, __nv_bfloat16* out,
                                      int g, int K, int KB, float s) {
    int R = g / (K >> 3), k = (g % (K >> 3)) << 3;
    const float4* src = (const float4*)(w + (size_t)R * K + k);
    float4 v0 = src[0], v1 = src[1];
    uint32_t pk[4];
    float e[8] = {v0.x, v0.y, v0.z, v0.w, v1.x, v1.y, v1.z, v1.w};
#pragma unroll
    for (int j = 0; j < 4; j++) {
        float q0 = rintf(fminf(fmaxf(e[2*j]   * s, -1.f), 1.f));
        float q1 = rintf(fminf(fmaxf(e[2*j+1] * s, -1.f), 1.f));
        __nv_bfloat162 b2 = __floats2bfloat162_rn(q0, q1);
        pk[j] = *(uint32_t*)&b2;
    }
    *(uint4*)((char*)out + tiled_off16(R, k, KB)) = make_uint4(pk[0], pk[1], pk[2], pk[3]);
}

// fused: blocks [0,2048) ternarize w_up; blocks [2048, 2048+TOKENS) rmsnorm+quant
__global__ void k_tern_rms(const float* __restrict__ wup,
                           const float* __restrict__ x, const float* __restrict__ nw) {
    if (blockIdx.x < 2048) {
        int g = blockIdx.x * 256 + threadIdx.x;     // 8-elem group over WSZ/8
        tern8(wup, g_wupq, g, HDIM, HDIM >> 6, 1.0f / g_mw[0]);
        return;
    }
    __shared__ float sh[256];
    __shared__ float s_inv, s_scale;
    int t = blockIdx.x - 2048, tid = threadIdx.x;
    float4 v = ((const float4*)(x + (size_t)t * HDIM))[tid];
    float4 w = ((const float4*)nw)[tid];
    float ss = v.x * v.x + v.y * v.y + v.z * v.z + v.w * v.w;
    sh[tid] = ss; __syncthreads();
    for (int o = 128; o > 0; o >>= 1) { if (tid < o) sh[tid] += sh[tid + o]; __syncthreads(); }
    if (tid == 0) s_inv = 1.0f / sqrtf(sh[0] * (1.0f / HDIM) + 1e-6f);
    __syncthreads();
    float inv = s_inv;
    float h0 = v.x * inv * w.x, h1 = v.y * inv * w.y, h2 = v.z * inv * w.z, h3 = v.w * inv * w.w;
    float m = fmaxf(fmaxf(fabsf(h0), fabsf(h1)), fmaxf(fabsf(h2), fabsf(h3)));
    sh[tid] = m; __syncthreads();
    for (int o = 128; o > 0; o >>= 1) { if (tid < o) sh[tid] = fmaxf(sh[tid], sh[tid + o]); __syncthreads(); }
    if (tid == 0) {
        float cm = fmaxf(sh[0], 1e-5f);
        s_scale = 127.0f / cm;
        g_mul1[t] = (cm / 127.0f) * g_mw[0];
        g_rowmax[t] = 0;
    }
    __syncthreads();
    float sc = s_scale;
    float q0 = rintf(fminf(fmaxf(h0 * sc, -128.f), 127.f));
    float q1 = rintf(fminf(fmaxf(h1 * sc, -128.f), 127.f));
    float q2 = rintf(fminf(fmaxf(h2 * sc, -128.f), 127.f));
    float q3 = rintf(fminf(fmaxf(h3 * sc, -128.f), 127.f));
    char* p = (char*)g_xq + tiled_off16(t, 4 * tid, HDIM >> 6);
    *(__nv_bfloat162*)p       = __floats2bfloat162_rn(q0, q1);
    *(__nv_bfloat162*)(p + 4) = __floats2bfloat162_rn(q2, q3);
}

// fused: blocks [0,2048) ternarize w_dn; blocks [2048, 2048+8192) relu^2-quant,
// 32 elems (64B) per thread with 4 independent load/store streams.
__global__ void k_relu2_terndn(const float* __restrict__ wdn) {
    if (blockIdx.x < 2048) {
        int g = blockIdx.x * 256 + threadIdx.x;
        tern8(wdn, g_wdnq, g, FDIM, FDIM >> 6, 1.0f / g_mw[1]);
        return;
    }
    size_t gi = (size_t)(blockIdx.x - 2048) * 256 + threadIdx.x;  // group-of-32 index
    int t = (int)(gi >> 7);                                       // 128 groups per row
    float mul1 = g_mul1[t];
    float rm = __int_as_float(g_rowmax[t]) * mul1;
    float sc2 = 127.0f / fmaxf(rm * rm, 1e-5f);
    const int4* src = (const int4*)(g_up + gi * 32);
    int f = (int)((gi & 127) << 5);
    int4 u[4];
#pragma unroll
    for (int q = 0; q < 4; q++) u[q] = src[q];                    // 4 independent 16B loads
#pragma unroll
    for (int q = 0; q < 4; q++) {
        uint32_t pk[4];
        const uint32_t* uw = (const uint32_t*)&u[q];
#pragma unroll
        for (int j = 0; j < 4; j++) {
            int lo = (int)(short)(uw[j] & 0xFFFF);
            int hi = (int)(short)(uw[j] >> 16);
            float a0 = fmaxf((float)lo, 0.f) * mul1;
            float a1 = fmaxf((float)hi, 0.f) * mul1;
            float q0 = rintf(fminf(a0 * a0 * sc2, 127.f));
            float q1 = rintf(fminf(a1 * a1 * sc2, 127.f));
            __nv_bfloat162 b2 = __floats2bfloat162_rn(q0, q1);
            pk[j] = *(uint32_t*)&b2;
        }
        *(uint4*)((char*)g_h2q + tiled_off16(t, f + q * 8, FDIM >> 6)) =
            make_uint4(pk[0], pk[1], pk[2], pk[3]);
    }
}

// ---------------- bf16 mma.sync GEMM, bulk-copy + mbarrier pipeline ----------------
// Tile 128x128x64; 8 warps = 2(M) x 4(N); warp tile 64x32; 3 stages; 2 CTAs/SM.
// EPI==1: store int16 (exact) to g_up + fused per-row relu-max.
// EPI==2: out = C*mul2[m] + resid (float).

#define STAGES    3
#define STAGE_B   32768
#define GEMM_SMEM (STAGES*STAGE_B)

template <int KTOT, int EPI>
__global__ void __launch_bounds__(256, 2)
k_gemm(const float* __restrict__ resid, float* __restrict__ out2) {
    extern __shared__ __align__(128) int8_t smem[];
    __shared__ __align__(8) uint64_t s_bar[2 * STAGES];
    __shared__ int s_rowmax[128];

    const __nv_bfloat16* A = (EPI == 1) ? g_xq   : g_h2q;
    const __nv_bfloat16* B = (EPI == 1) ? g_wupq : g_wdnq;
    const int KIT = KTOT / 64;
    const int KB  = KTOT / 64;

    int tid = threadIdx.x, wid = tid >> 5, lane = tid & 31;
    int wm = wid & 1, wn = wid >> 1;
    int mb = blockIdx.y, nb = blockIdx.x;
    int m0 = mb * 128, n0 = nb * 128;
    int tg = lane & 3, gp = lane >> 2;
    uint32_t sbase = smem_u32(smem);
    uint32_t barb  = smem_u32(s_bar);

    if (EPI == 1 && tid < 128) s_rowmax[tid] = 0;
    if (tid == 0) {
#pragma unroll
        for (int s = 0; s < STAGES; s++) {
            MBARRIER_INIT(barb + s * 8, 1);             // full: tx-based
            MBARRIER_INIT(barb + (STAGES + s) * 8, 8);  // empty: one arrive per warp
        }
        asm volatile("fence.proxy.async.shared::cta;" ::: "memory");
    }
    __syncthreads();

    int aRow = wm * 64 + (lane & 15);
    int aCsel = lane >> 4;
    int bRow = wn * 32 + ((lane >> 3) & 1) * 8 + (lane & 7);
    int bCsel = lane >> 4;

    float acc[4][4][4];
#pragma unroll
    for (int i = 0; i < 4; i++)
#pragma unroll
        for (int j = 0; j < 4; j++)
#pragma unroll
            for (int r = 0; r < 4; r++) acc[i][j][r] = 0.f;

    int pstage = 0, pphase = 1;
    int cphase = 0;

    auto produce = [&](int kit) {
        uint32_t fb = barb + pstage * 8;
        MBARRIER_WAIT_PARITY_RELAXED(barb + (STAGES + pstage) * 8, pphase);
        MBARRIER_EXPECT_TX(fb, 32768u);
        uint32_t dst = sbase + (uint32_t)pstage * STAGE_B;
        cp_bulk(dst,          (const char*)A + ((size_t)(mb * KB + kit) << 14), 16384u, fb);
        cp_bulk(dst + 16384u, (const char*)B + ((size_t)(nb * KB + kit) << 14), 16384u, fb);
        if (++pstage == STAGES) { pstage = 0; pphase ^= 1; }
    };

    if (tid == 0) {
        produce(0);
        produce(1);
    }

    int cur = 0;
    for (int it = 0; it < KIT; it++) {
        if (tid == 0 && it + STAGES - 1 < KIT) produce(it + STAGES - 1);

        MBARRIER_WAIT_PARITY(barb + cur * 8, cphase);
        uint32_t sA = sbase + (uint32_t)cur * STAGE_B;
        uint32_t sB = sA + 16384u;

#pragma unroll
        for (int ks = 0; ks < 4; ks++) {
            uint32_t a[4][4], b[2][4];
#pragma unroll
            for (int mt = 0; mt < 4; mt++) {
                int row = aRow + mt * 16;
                int c4 = (2 * ks + aCsel) ^ (row & 7);
                ldm_x4(a[mt], sA + row * 128 + (c4 << 4));
            }
#pragma unroll
            for (int np = 0; np < 2; np++) {
                int row = bRow + np * 16;
                int c4 = (2 * ks + bCsel) ^ (row & 7);
                ldm_x4(b[np], sB + row * 128 + (c4 << 4));
            }
            if (ks == 3 && lane == 0) MBARRIER_ARRIVE(barb + (STAGES + cur) * 8);
#pragma unroll
            for (int mt = 0; mt < 4; mt++)
#pragma unroll
                for (int np = 0; np < 2; np++)
#pragma unroll
                    for (int h = 0; h < 2; h++)
                        mma_bf16(acc[mt][np * 2 + h], a[mt], b[np][h], b[np][h + 2]);
        }
        if (++cur == STAGES) { cur = 0; cphase ^= 1; }
    }

    // ---------------- epilogue ----------------
    if (EPI == 1) {
#pragma unroll
        for (int mt = 0; mt < 4; mt++) {
            int lr0 = wm * 64 + mt * 16 + gp;
            float mx0 = 0.f, mx1 = 0.f;
#pragma unroll
            for (int nt = 0; nt < 4; nt++) {
                int col = n0 + wn * 32 + nt * 8 + tg * 2;
                int16_t* d0 = g_up + (size_t)(m0 + lr0) * FDIM + col;
                int16_t* d1 = g_up + (size_t)(m0 + lr0 + 8) * FDIM + col;
                int v00 = __float2int_rn(acc[mt][nt][0]);
                int v01 = __float2int_rn(acc[mt][nt][1]);
                int v10 = __float2int_rn(acc[mt][nt][2]);
                int v11 = __float2int_rn(acc[mt][nt][3]);
                *(uint32_t*)d0 = (uint32_t)(v00 & 0xFFFF) | ((uint32_t)v01 << 16);
                *(uint32_t*)d1 = (uint32_t)(v10 & 0xFFFF) | ((uint32_t)v11 << 16);
                mx0 = fmaxf(mx0, fmaxf(acc[mt][nt][0], acc[mt][nt][1]));
                mx1 = fmaxf(mx1, fmaxf(acc[mt][nt][2], acc[mt][nt][3]));
            }
            mx0 = fmaxf(mx0, __shfl_xor_sync(0xFFFFFFFFu, mx0, 1));
            mx0 = fmaxf(mx0, __shfl_xor_sync(0xFFFFFFFFu, mx0, 2));
            mx1 = fmaxf(mx1, __shfl_xor_sync(0xFFFFFFFFu, mx1, 1));
            mx1 = fmaxf(mx1, __shfl_xor_sync(0xFFFFFFFFu, mx1, 2));
            if (tg == 0) {
                atomicMax(&s_rowmax[lr0], __float_as_int(mx0));
                atomicMax(&s_rowmax[lr0 + 8], __float_as_int(mx1));
            }
        }
        __syncthreads();
        if (tid < 128) atomicMax(&g_rowmax[m0 + tid], s_rowmax[tid]);
    } else {
#pragma unroll
        for (int mt = 0; mt < 4; mt++) {
            int r0 = m0 + wm * 64 + mt * 16 + gp;
            int r1 = r0 + 8;
            float m1a = g_mul1[r0], m1b = g_mul1[r1];
            float rma = __int_as_float(g_rowmax[r0]) * m1a;
            float rmb = __int_as_float(g_rowmax[r1]) * m1b;
            float mul2a = (fmaxf(rma * rma, 1e-5f) / 127.0f) * g_mw[1];
            float mul2b = (fmaxf(rmb * rmb, 1e-5f) / 127.0f) * g_mw[1];
#pragma unroll
            for (int nt = 0; nt < 4; nt++) {
                int col = n0 + wn * 32 + nt * 8 + tg * 2;
                const float2 ra = *(const float2*)(resid + (size_t)r0 * HDIM + col);
                const float2 rb = *(const float2*)(resid + (size_t)r1 * HDIM + col);
                float2 oa, ob;
                oa.x = acc[mt][nt][0] * mul2a + ra.x;
                oa.y = acc[mt][nt][1] * mul2a + ra.y;
                ob.x = acc[mt][nt][2] * mul2b + rb.x;
                ob.y = acc[mt][nt][3] * mul2b + rb.y;
                *(float2*)(out2 + (size_t)r0 * HDIM + col) = oa;
                *(float2*)(out2 + (size_t)r1 * HDIM + col) = ob;
            }
        }
    }
}

// ---------------- launch ----------------
extern "C" void kernel_launch(void* const* d_in, const int* in_sizes, int n_in,
                              void* d_out, int out_size) {
    const float* x   = (const float*)d_in[0];
    const float* nw  = (const float*)d_in[1];
    const float* wup = (const float*)d_in[2];
    const float* wdn = (const float*)d_in[3];
    float* out = (float*)d_out;

    cudaFuncSetAttribute(k_gemm<1024, 1>, cudaFuncAttributeMaxDynamicSharedMemorySize, GEMM_SMEM);
    cudaFuncSetAttribute(k_gemm<4096, 2>, cudaFuncAttributeMaxDynamicSharedMemorySize, GEMM_SMEM);

    k_reduce_abs<<<2048, 256>>>(wup, wdn);                                   // 1
    k_finalize_mw<<<1, 256>>>();                                             // 2
    k_tern_rms<<<2048 + TOKENS, 256>>>(wup, x, nw);                          // 3
    k_gemm<1024, 1><<<dim3(FDIM / 128, TOKENS / 128), 256, GEMM_SMEM>>>(nullptr, nullptr);  // 4 (profiled)
    k_relu2_terndn<<<2048 + (int)((size_t)TOKENS * FDIM / 32 / 256), 256>>>(wdn);           // 5
    k_gemm<4096, 2><<<dim3(HDIM / 128, TOKENS / 128), 256, GEMM_SMEM>>>(x, out);            // 6
}

// round 17
// speedup vs baseline: 1.0793x; 1.0109x over previous
#include <cuda_runtime.h>
#include <cuda_bf16.h>
#include <cstdint>

#define TOKENS 16384
#define HDIM   1024
#define FDIM   4096
#define WSZ    (FDIM*HDIM)

// ---------------- scratch (static device, no allocations) ----------------
// Tiled bf16 layout for all GEMM operands: tile = 128 rows x 64 k = 16384 B,
// tiles ordered [row_block][k_block]. Within a tile, row r (128 B) holds 8
// 16B chunks, physically at chunk c ^ (r & 7)  -> ldmatrix conflict-free.
__device__ __align__(1024) __nv_bfloat16 g_xq  [(size_t)TOKENS*HDIM];   // 32 MB
__device__ __align__(1024) __nv_bfloat16 g_wupq[WSZ];                   //  8 MB
__device__ __align__(1024) __nv_bfloat16 g_wdnq[WSZ];                   //  8 MB
__device__ __align__(1024) __nv_bfloat16 g_h2q [(size_t)TOKENS*FDIM];   // 128 MB
__device__ int16_t g_up [(size_t)TOKENS*FDIM];   // 128 MB GEMM1 result (exact ints, linear)
__device__ float  g_mul1[TOKENS];
__device__ int    g_rowmax[TOKENS];              // float bits, >= 0
__device__ float  g_part[2048];
__device__ float  g_mw[2];

// byte address of bf16 element (row R, col k) in tiled layout (KB k-blocks)
__device__ __forceinline__ size_t tiled_off16(int R, int k, int KB) {
    int r = R & 127, mb = R >> 7, kb = k >> 6;
    int c  = (k & 63) >> 3;           // chunk 0..7
    int c4 = c ^ (r & 7);
    return ((size_t)(mb * KB + kb) << 14) + (size_t)(r * 128 + (c4 << 4) + ((k & 7) << 1));
}

// ---------------- PTX helpers ----------------
__device__ __forceinline__ uint32_t smem_u32(const void* p) {
    uint32_t a;
    asm("{ .reg .u64 t; cvta.to.shared.u64 t, %1; cvt.u32.u64 %0, t; }" : "=r"(a) : "l"(p));
    return a;
}
__device__ __forceinline__ void mma_bf16(float* c, const uint32_t* a, uint32_t b0, uint32_t b1) {
    asm volatile(
        "mma.sync.aligned.m16n8k16.row.col.f32.bf16.bf16.f32 "
        "{%0,%1,%2,%3}, {%4,%5,%6,%7}, {%8,%9}, {%0,%1,%2,%3};"
        : "+f"(c[0]), "+f"(c[1]), "+f"(c[2]), "+f"(c[3])
        : "r"(a[0]), "r"(a[1]), "r"(a[2]), "r"(a[3]), "r"(b0), "r"(b1));
}
__device__ __forceinline__ void ldm_x4(uint32_t* r, uint32_t addr) {
    asm volatile("ldmatrix.sync.aligned.m8n8.x4.shared.b16 {%0,%1,%2,%3}, [%4];"
        : "=r"(r[0]), "=r"(r[1]), "=r"(r[2]), "=r"(r[3]) : "r"(addr));
}
__device__ __forceinline__ void cp_bulk(uint32_t dst, const void* src, uint32_t bytes, uint32_t mbar) {
    asm volatile(
        "cp.async.bulk.shared::cta.global.mbarrier::complete_tx::bytes [%0], [%1], %2, [%3];"
        :: "r"(dst), "l"(src), "r"(bytes), "r"(mbar) : "memory");
}
#define MBARRIER_INIT(addr, cnt) \
    asm volatile("mbarrier.init.shared.b64 [%0], %1;" :: "r"((uint32_t)(addr)), "r"((uint32_t)(cnt)) : "memory")
#define MBARRIER_EXPECT_TX(addr, tx) \
    asm volatile("mbarrier.arrive.expect_tx.shared.b64 _, [%0], %1;" :: "r"((uint32_t)(addr)), "r"((uint32_t)(tx)) : "memory")
#define MBARRIER_ARRIVE(addr) \
    asm volatile("mbarrier.arrive.shared.b64 _, [%0];" :: "r"((uint32_t)(addr)) : "memory")
#define MBARRIER_WAIT_PARITY(addr, parity) do {                                   \
    uint32_t _mbar = (uint32_t)(addr);                                            \
    uint32_t _par  = (uint32_t)(parity);                                          \
    asm volatile(                                                                 \
        "{\n\t.reg .pred P1;\n\t"                                                 \
        "WAIT_LOOP_%=:\n\t"                                                       \
        "mbarrier.try_wait.parity.acquire.cta.shared::cta.b64 P1, [%0], %1, 0x989680;\n\t" \
        "@P1 bra.uni WAIT_DONE_%=;\n\t"                                           \
        "bra.uni WAIT_LOOP_%=;\n\t"                                               \
        "WAIT_DONE_%=:\n\t}"                                                      \
        :: "r"(_mbar), "r"(_par) : "memory");                                     \
} while (0)
#define MBARRIER_WAIT_PARITY_RELAXED(addr, parity) do {                           \
    uint32_t _mbar = (uint32_t)(addr);                                            \
    uint32_t _par  = (uint32_t)(parity);                                          \
    asm volatile(                                                                 \
        "{\n\t.reg .pred P1;\n\t"                                                 \
        "WAIT_LOOP_%=:\n\t"                                                       \
        "mbarrier.try_wait.parity.relaxed.cta.shared::cta.b64 P1, [%0], %1, 0x989680;\n\t" \
        "@P1 bra.uni WAIT_DONE_%=;\n\t"                                           \
        "bra.uni WAIT_LOOP_%=;\n\t"                                               \
        "WAIT_DONE_%=:\n\t}"                                                      \
        :: "r"(_mbar), "r"(_par) : "memory");                                     \
} while (0)

// ---------------- elementwise kernels ----------------

// warp shfl sum + one sync + redundant 8-partial reduce in registers
__global__ void k_reduce_abs(const float* __restrict__ wup, const float* __restrict__ wdn) {
    __shared__ float sh[8];
    int b = blockIdx.x;
    const float4* p = (const float4*)((b < 1024) ? wup : wdn);
    int bb = b & 1023;
    int tid = threadIdx.x, lane = tid & 31, w = tid >> 5;
    float s = 0.f;
    int base = bb * 1024 + tid;
#pragma unroll
    for (int i = 0; i < 4; i++) {
        float4 v = p[base + i * 256];
        s += fabsf(v.x) + fabsf(v.y) + fabsf(v.z) + fabsf(v.w);
    }
#pragma unroll
    for (int o = 16; o > 0; o >>= 1) s += __shfl_xor_sync(0xFFFFFFFFu, s, o);
    if (lane == 0) sh[w] = s;
    __syncthreads();
    if (tid == 0) {
        float t = 0.f;
#pragma unroll
        for (int i = 0; i < 8; i++) t += sh[i];
        g_part[b] = t;
    }
}

__global__ void k_finalize_mw() {
    __shared__ float sh[256];
    for (int half = 0; half < 2; half++) {
        float s = 0.f;
        for (int i = threadIdx.x; i < 1024; i += 256) s += g_part[half * 1024 + i];
        sh[threadIdx.x] = s; __syncthreads();
        for (int o = 128; o > 0; o >>= 1) {
            if (threadIdx.x < o) sh[threadIdx.x] += sh[threadIdx.x + o];
            __syncthreads();
        }
        if (threadIdx.x == 0) g_mw[half] = fmaxf(sh[0] / (float)WSZ, 1e-5f);
        __syncthreads();
    }
}

// ternarize 8 consecutive k per thread -> one full 16B tiled chunk store
__device__ __forceinline__ void tern8(const float* __restrict__ w, __nv_bfloat16* out,
                                      int g, int K, int KB, float s) {
    int R = g / (K >> 3), k = (g % (K >> 3)) << 3;
    const float4* src = (const float4*)(w + (size_t)R * K + k);
    float4 v0 = src[0], v1 = src[1];
    uint32_t pk[4];
    float e[8] = {v0.x, v0.y, v0.z, v0.w, v1.x, v1.y, v1.z, v1.w};
#pragma unroll
    for (int j = 0; j < 4; j++) {
        float q0 = rintf(fminf(fmaxf(e[2*j]   * s, -1.f), 1.f));
        float q1 = rintf(fminf(fmaxf(e[2*j+1] * s, -1.f), 1.f));
        __nv_bfloat162 b2 = __floats2bfloat162_rn(q0, q1);
        pk[j] = *(uint32_t*)&b2;
    }
    *(uint4*)((char*)out + tiled_off16(R, k, KB)) = make_uint4(pk[0], pk[1], pk[2], pk[3]);
}

// fused: blocks [0,2048) ternarize w_up; blocks [2048, 2048+TOKENS) rmsnorm+quant.
// Both reductions are warp-shuffle based: one __syncthreads each.
__global__ void k_tern_rms(const float* __restrict__ wup,
                           const float* __restrict__ x, const float* __restrict__ nw) {
    if (blockIdx.x < 2048) {
        int g = blockIdx.x * 256 + threadIdx.x;     // 8-elem group over WSZ/8
        tern8(wup, g_wupq, g, HDIM, HDIM >> 6, 1.0f / g_mw[0]);
        return;
    }
    __shared__ float shs[8];
    __shared__ float shm[8];
    int t = blockIdx.x - 2048, tid = threadIdx.x;
    int lane = tid & 31, wrp = tid >> 5;
    float4 v = ((const float4*)(x + (size_t)t * HDIM))[tid];
    float4 w = ((const float4*)nw)[tid];
    float ss = v.x * v.x + v.y * v.y + v.z * v.z + v.w * v.w;
#pragma unroll
    for (int o = 16; o > 0; o >>= 1) ss += __shfl_xor_sync(0xFFFFFFFFu, ss, o);
    if (lane == 0) shs[wrp] = ss;
    __syncthreads();
    float p = shs[tid & 7];
    p += __shfl_xor_sync(0xFFFFFFFFu, p, 1);
    p += __shfl_xor_sync(0xFFFFFFFFu, p, 2);
    p += __shfl_xor_sync(0xFFFFFFFFu, p, 4);
    float inv = 1.0f / sqrtf(p * (1.0f / HDIM) + 1e-6f);

    float h0 = v.x * inv * w.x, h1 = v.y * inv * w.y, h2 = v.z * inv * w.z, h3 = v.w * inv * w.w;
    float m = fmaxf(fmaxf(fabsf(h0), fabsf(h1)), fmaxf(fabsf(h2), fabsf(h3)));
#pragma unroll
    for (int o = 16; o > 0; o >>= 1) m = fmaxf(m, __shfl_xor_sync(0xFFFFFFFFu, m, o));
    if (lane == 0) shm[wrp] = m;
    __syncthreads();
    float q = shm[tid & 7];
    q = fmaxf(q, __shfl_xor_sync(0xFFFFFFFFu, q, 1));
    q = fmaxf(q, __shfl_xor_sync(0xFFFFFFFFu, q, 2));
    q = fmaxf(q, __shfl_xor_sync(0xFFFFFFFFu, q, 4));
    float cm = fmaxf(q, 1e-5f);
    float sc = 127.0f / cm;
    if (tid == 0) {
        g_mul1[t] = (cm / 127.0f) * g_mw[0];
        g_rowmax[t] = 0;
    }
    float q0 = rintf(fminf(fmaxf(h0 * sc, -128.f), 127.f));
    float q1 = rintf(fminf(fmaxf(h1 * sc, -128.f), 127.f));
    float q2 = rintf(fminf(fmaxf(h2 * sc, -128.f), 127.f));
    float q3 = rintf(fminf(fmaxf(h3 * sc, -128.f), 127.f));
    char* pp = (char*)g_xq + tiled_off16(t, 4 * tid, HDIM >> 6);
    *(__nv_bfloat162*)pp       = __floats2bfloat162_rn(q0, q1);
    *(__nv_bfloat162*)(pp + 4) = __floats2bfloat162_rn(q2, q3);
}

// fused: blocks [0,2048) ternarize w_dn; blocks [2048, 2048+8192) relu^2-quant,
// 32 elems (64B) per thread with 4 independent load/store streams.
__global__ void k_relu2_terndn(const float* __restrict__ wdn) {
    if (blockIdx.x < 2048) {
        int g = blockIdx.x * 256 + threadIdx.x;
        tern8(wdn, g_wdnq, g, FDIM, FDIM >> 6, 1.0f / g_mw[1]);
        return;
    }
    size_t gi = (size_t)(blockIdx.x - 2048) * 256 + threadIdx.x;  // group-of-32 index
    int t = (int)(gi >> 7);                                       // 128 groups per row
    float mul1 = g_mul1[t];
    float rm = __int_as_float(g_rowmax[t]) * mul1;
    float sc2 = 127.0f / fmaxf(rm * rm, 1e-5f);
    const int4* src = (const int4*)(g_up + gi * 32);
    int f = (int)((gi & 127) << 5);
    int4 u[4];
#pragma unroll
    for (int q = 0; q < 4; q++) u[q] = src[q];                    // 4 independent 16B loads
#pragma unroll
    for (int q = 0; q < 4; q++) {
        uint32_t pk[4];
        const uint32_t* uw = (const uint32_t*)&u[q];
#pragma unroll
        for (int j = 0; j < 4; j++) {
            int lo = (int)(short)(uw[j] & 0xFFFF);
            int hi = (int)(short)(uw[j] >> 16);
            float a0 = fmaxf((float)lo, 0.f) * mul1;
            float a1 = fmaxf((float)hi, 0.f) * mul1;
            float q0 = rintf(fminf(a0 * a0 * sc2, 127.f));
            float q1 = rintf(fminf(a1 * a1 * sc2, 127.f));
            __nv_bfloat162 b2 = __floats2bfloat162_rn(q0, q1);
            pk[j] = *(uint32_t*)&b2;
        }
        *(uint4*)((char*)g_h2q + tiled_off16(t, f + q * 8, FDIM >> 6)) =
            make_uint4(pk[0], pk[1], pk[2], pk[3]);
    }
}

// ---------------- bf16 mma.sync GEMM, bulk-copy + mbarrier pipeline ----------------
// Tile 128x128x64; 8 warps = 2(M) x 4(N); warp tile 64x32; 3 stages; 2 CTAs/SM.
// EPI==1: store int16 (exact) to g_up + fused per-row relu-max.
// EPI==2: out = C*mul2[m] + resid (float).

#define STAGES    3
#define STAGE_B   32768
#define GEMM_SMEM (STAGES*STAGE_B)

template <int KTOT, int EPI>
__global__ void __launch_bounds__(256, 2)
k_gemm(const float* __restrict__ resid, float* __restrict__ out2) {
    extern __shared__ __align__(128) int8_t smem[];
    __shared__ __align__(8) uint64_t s_bar[2 * STAGES];
    __shared__ int s_rowmax[128];

    const __nv_bfloat16* A = (EPI == 1) ? g_xq   : g_h2q;
    const __nv_bfloat16* B = (EPI == 1) ? g_wupq : g_wdnq;
    const int KIT = KTOT / 64;
    const int KB  = KTOT / 64;

    int tid = threadIdx.x, wid = tid >> 5, lane = tid & 31;
    int wm = wid & 1, wn = wid >> 1;
    int mb = blockIdx.y, nb = blockIdx.x;
    int m0 = mb * 128, n0 = nb * 128;
    int tg = lane & 3, gp = lane >> 2;
    uint32_t sbase = smem_u32(smem);
    uint32_t barb  = smem_u32(s_bar);

    if (EPI == 1 && tid < 128) s_rowmax[tid] = 0;
    if (tid == 0) {
#pragma unroll
        for (int s = 0; s < STAGES; s++) {
            MBARRIER_INIT(barb + s * 8, 1);             // full: tx-based
            MBARRIER_INIT(barb + (STAGES + s) * 8, 8);  // empty: one arrive per warp
        }
        asm volatile("fence.proxy.async.shared::cta;" ::: "memory");
    }
    __syncthreads();

    int aRow = wm * 64 + (lane & 15);
    int aCsel = lane >> 4;
    int bRow = wn * 32 + ((lane >> 3) & 1) * 8 + (lane & 7);
    int bCsel = lane >> 4;

    float acc[4][4][4];
#pragma unroll
    for (int i = 0; i < 4; i++)
#pragma unroll
        for (int j = 0; j < 4; j++)
#pragma unroll
            for (int r = 0; r < 4; r++) acc[i][j][r] = 0.f;

    int pstage = 0, pphase = 1;
    int cphase = 0;

    auto produce = [&](int kit) {
        uint32_t fb = barb + pstage * 8;
        MBARRIER_WAIT_PARITY_RELAXED(barb + (STAGES + pstage) * 8, pphase);
        MBARRIER_EXPECT_TX(fb, 32768u);
        uint32_t dst = sbase + (uint32_t)pstage * STAGE_B;
        cp_bulk(dst,          (const char*)A + ((size_t)(mb * KB + kit) << 14), 16384u, fb);
        cp_bulk(dst + 16384u, (const char*)B + ((size_t)(nb * KB + kit) << 14), 16384u, fb);
        if (++pstage == STAGES) { pstage = 0; pphase ^= 1; }
    };

    if (tid == 0) {
        produce(0);
        produce(1);
    }

    int cur = 0;
    for (int it = 0; it < KIT; it++) {
        if (tid == 0 && it + STAGES - 1 < KIT) produce(it + STAGES - 1);

        MBARRIER_WAIT_PARITY(barb + cur * 8, cphase);
        uint32_t sA = sbase + (uint32_t)cur * STAGE_B;
        uint32_t sB = sA + 16384u;

#pragma unroll
        for (int ks = 0; ks < 4; ks++) {
            uint32_t a[4][4], b[2][4];
#pragma unroll
            for (int mt = 0; mt < 4; mt++) {
                int row = aRow + mt * 16;
                int c4 = (2 * ks + aCsel) ^ (row & 7);
                ldm_x4(a[mt], sA + row * 128 + (c4 << 4));
            }
#pragma unroll
            for (int np = 0; np < 2; np++) {
                int row = bRow + np * 16;
                int c4 = (2 * ks + bCsel) ^ (row & 7);
                ldm_x4(b[np], sB + row * 128 + (c4 << 4));
            }
            if (ks == 3 && lane == 0) MBARRIER_ARRIVE(barb + (STAGES + cur) * 8);
#pragma unroll
            for (int mt = 0; mt < 4; mt++)
#pragma unroll
                for (int np = 0; np < 2; np++)
#pragma unroll
                    for (int h = 0; h < 2; h++)
                        mma_bf16(acc[mt][np * 2 + h], a[mt], b[np][h], b[np][h + 2]);
        }
        if (++cur == STAGES) { cur = 0; cphase ^= 1; }
    }

    // ---------------- epilogue ----------------
    if (EPI == 1) {
#pragma unroll
        for (int mt = 0; mt < 4; mt++) {
            int lr0 = wm * 64 + mt * 16 + gp;
            float mx0 = 0.f, mx1 = 0.f;
#pragma unroll
            for (int nt = 0; nt < 4; nt++) {
                int col = n0 + wn * 32 + nt * 8 + tg * 2;
                int16_t* d0 = g_up + (size_t)(m0 + lr0) * FDIM + col;
                int16_t* d1 = g_up + (size_t)(m0 + lr0 + 8) * FDIM + col;
                int v00 = __float2int_rn(acc[mt][nt][0]);
                int v01 = __float2int_rn(acc[mt][nt][1]);
                int v10 = __float2int_rn(acc[mt][nt][2]);
                int v11 = __float2int_rn(acc[mt][nt][3]);
                *(uint32_t*)d0 = (uint32_t)(v00 & 0xFFFF) | ((uint32_t)v01 << 16);
                *(uint32_t*)d1 = (uint32_t)(v10 & 0xFFFF) | ((uint32_t)v11 << 16);
                mx0 = fmaxf(mx0, fmaxf(acc[mt][nt][0], acc[mt][nt][1]));
                mx1 = fmaxf(mx1, fmaxf(acc[mt][nt][2], acc[mt][nt][3]));
            }
            mx0 = fmaxf(mx0, __shfl_xor_sync(0xFFFFFFFFu, mx0, 1));
            mx0 = fmaxf(mx0, __shfl_xor_sync(0xFFFFFFFFu, mx0, 2));
            mx1 = fmaxf(mx1, __shfl_xor_sync(0xFFFFFFFFu, mx1, 1));
            mx1 = fmaxf(mx1, __shfl_xor_sync(0xFFFFFFFFu, mx1, 2));
            if (tg == 0) {
                atomicMax(&s_rowmax[lr0], __float_as_int(mx0));
                atomicMax(&s_rowmax[lr0 + 8], __float_as_int(mx1));
            }
        }
        __syncthreads();
        if (tid < 128) atomicMax(&g_rowmax[m0 + tid], s_rowmax[tid]);
    } else {
#pragma unroll
        for (int mt = 0; mt < 4; mt++) {
            int r0 = m0 + wm * 64 + mt * 16 + gp;
            int r1 = r0 + 8;
            float m1a = g_mul1[r0], m1b = g_mul1[r1];
            float rma = __int_as_float(g_rowmax[r0]) * m1a;
            float rmb = __int_as_float(g_rowmax[r1]) * m1b;
            float mul2a = (fmaxf(rma * rma, 1e-5f) / 127.0f) * g_mw[1];
            float mul2b = (fmaxf(rmb * rmb, 1e-5f) / 127.0f) * g_mw[1];
#pragma unroll
            for (int nt = 0; nt < 4; nt++) {
                int col = n0 + wn * 32 + nt * 8 + tg * 2;
                const float2 ra = *(const float2*)(resid + (size_t)r0 * HDIM + col);
                const float2 rb = *(const float2*)(resid + (size_t)r1 * HDIM + col);
                float2 oa, ob;
                oa.x = acc[mt][nt][0] * mul2a + ra.x;
                oa.y = acc[mt][nt][1] * mul2a + ra.y;
                ob.x = acc[mt][nt][2] * mul2b + rb.x;
                ob.y = acc[mt][nt][3] * mul2b + rb.y;
                *(float2*)(out2 + (size_t)r0 * HDIM + col) = oa;
                *(float2*)(out2 + (size_t)r1 * HDIM + col) = ob;
            }
        }
    }
}

// ---------------- launch ----------------
extern "C" void kernel_launch(void* const* d_in, const int* in_sizes, int n_in,
                              void* d_out, int out_size) {
    const float* x   = (const float*)d_in[0];
    const float* nw  = (const float*)d_in[1];
    const float* wup = (const float*)d_in[2];
    const float* wdn = (const float*)d_in[3];
    float* out = (float*)d_out;

    cudaFuncSetAttribute(k_gemm<1024, 1>, cudaFuncAttributeMaxDynamicSharedMemorySize, GEMM_SMEM);
    cudaFuncSetAttribute(k_gemm<4096, 2>, cudaFuncAttributeMaxDynamicSharedMemorySize, GEMM_SMEM);

    k_reduce_abs<<<2048, 256>>>(wup, wdn);                                   // 1
    k_finalize_mw<<<1, 256>>>();                                             // 2
    k_tern_rms<<<2048 + TOKENS, 256>>>(wup, x, nw);                          // 3
    k_gemm<1024, 1><<<dim3(FDIM / 128, TOKENS / 128), 256, GEMM_SMEM>>>(nullptr, nullptr);  // 4 (profiled)
    k_relu2_terndn<<<2048 + (int)((size_t)TOKENS * FDIM / 32 / 256), 256>>>(wdn);           // 5
    k_gemm<4096, 2><<<dim3(HDIM / 128, TOKENS / 128), 256, GEMM_SMEM>>>(x, out);            // 6
}